// round 15
// baseline (speedup 1.0000x reference)
#include <cuda_runtime.h>
#include <cuda_bf16.h>
#include <cstdint>

// NonLocalModule (no softmax) collapsed via associativity, fully fused:
//   out = X + E' X + e0, G = X X^T (128x128/batch), A = Wo Wv, Bm = Wk^T Wq,
//   E' = (1/N)[A G Bm + (A s) w2^T + u (Bm^T s)^T] + u w2^T
//   e0 = (1/N)[(A G) kq + (A s) beta + u (s.kq)] + u beta + bo
// Single persistent kernel, 132 blocks (all co-resident):
//   phase A: blocks 0..99 gram (bf16 mma.sync, X tile stays warm in smem);
//            blocks 100..131 prep (A, Bm, bias vectors; packed f32x2).
//   bar1 (wait: R blocks 0..31, B blocks 100..115, s blocks 128..129)
//   phase R: blocks 0..31 reduce bf16 G partials -> bf16 G;
//            blocks 128/129 reduce s, skq AND t1 = Bm^T s, t2 = A s
//            (hoisted off B's critical path); B blocks prefetch A/Bm as bf16.
//   bar2 (wait: B blocks)
//   phase B: 16 B blocks (16-row slabs): P = A G and E' = P Bm via bf16
//            mma.sync (G symmetric; Bm via ldsm.trans); e0 from fp32 P.
//   bar3 (wait: tile blocks)
//   phase C: tile blocks out = X + E' X + e0 (reuse warm X tile).
// Barriers: monotonic counters; ALL blocks arrive at all three (replay-safe).

#define C     128
#define NPIX  6400
#define BATCH 2
#define NT    50
#define NTILE 100
#define NTOT  132

// ---------------- device scratch (no allocations allowed) --------------------
__device__ __nv_bfloat16 g_Gpb[BATCH*NT*C*C];  // bf16 gram partials
__device__ float g_sp[BATCH*NT*C];
__device__ __nv_bfloat16 g_Gb16[BATCH*C*C];    // reduced G, bf16
__device__ float g_s [BATCH*C];
__device__ float g_A [C*C];
__device__ float g_Bm[C*C];
__device__ __nv_bfloat16 g_Ebf[BATCH*C*C];     // E' bf16, row-major [r][c]
__device__ float g_e0[BATCH*C];
__device__ float g_u [C];
__device__ float g_w2[C];
__device__ float g_kq[C];
__device__ float g_t1v[BATCH*C];               // (Bm^T s)[c]
__device__ float g_t2v[BATCH*C];               // (A s)[r]
__device__ float g_skq[BATCH];
__device__ float g_beta;
__device__ unsigned g_bar1, g_bar2, g_bar3;    // monotonic grid barriers

// ---------------- helpers -----------------------------------------------------
__device__ __forceinline__ void fma2(unsigned long long &acc,
                                     unsigned long long a, unsigned long long b) {
    asm("fma.rn.f32x2 %0, %1, %2, %0;" : "+l"(acc) : "l"(a), "l"(b));
}
__device__ __forceinline__ unsigned long long dup2(float a) {
    unsigned long long r; unsigned ai = __float_as_uint(a);
    asm("mov.b64 %0, {%1, %1};" : "=l"(r) : "r"(ai));
    return r;
}
__device__ __forceinline__ float2 unp2(unsigned long long v) {
    float2 r;
    r.x = __uint_as_float((unsigned)(v & 0xffffffffull));
    r.y = __uint_as_float((unsigned)(v >> 32));
    return r;
}
__device__ __forceinline__ float red16(float p) {
    p += __shfl_down_sync(0xffffffffu, p, 8, 16);
    p += __shfl_down_sync(0xffffffffu, p, 4, 16);
    p += __shfl_down_sync(0xffffffffu, p, 2, 16);
    p += __shfl_down_sync(0xffffffffu, p, 1, 16);
    return p;
}
__device__ __forceinline__ uint32_t smem_u32(const void* p) {
    uint32_t a;
    asm("{ .reg .u64 t; cvta.to.shared.u64 t, %1; cvt.u32.u64 %0, t; }"
        : "=r"(a) : "l"(p));
    return a;
}
// monotonic barriers: every block arrives at every counter exactly once/launch
__device__ __forceinline__ void gbar_arrive(unsigned* ctr) {
    __syncthreads();
    if (threadIdx.x == 0) { __threadfence(); atomicAdd(ctr, 1u); }
}
__device__ __forceinline__ void gbar_wait(unsigned* ctr, unsigned tot) {
    __syncthreads();
    if (threadIdx.x == 0) {
        __threadfence();
        const unsigned old = atomicAdd(ctr, 1u);
        const unsigned tgt = (old / tot + 1u) * tot;
        volatile unsigned* p = ctr;
        while (*p < tgt) {}
    }
    __syncthreads();
    __threadfence();
}
__device__ __forceinline__ void ldsm_x4(uint32_t* r, uint32_t addr) {
    asm volatile("ldmatrix.sync.aligned.m8n8.x4.shared.b16 {%0,%1,%2,%3}, [%4];"
        : "=r"(r[0]), "=r"(r[1]), "=r"(r[2]), "=r"(r[3]) : "r"(addr));
}
__device__ __forceinline__ void ldsm_x2(uint32_t* r, uint32_t addr) {
    asm volatile("ldmatrix.sync.aligned.m8n8.x2.shared.b16 {%0,%1}, [%2];"
        : "=r"(r[0]), "=r"(r[1]) : "r"(addr));
}
__device__ __forceinline__ void ldsm_x2_trans(uint32_t* r, uint32_t addr) {
    asm volatile("ldmatrix.sync.aligned.m8n8.x2.trans.shared.b16 {%0,%1}, [%2];"
        : "=r"(r[0]), "=r"(r[1]) : "r"(addr));
}
__device__ __forceinline__ void mma16816(float* d, const uint32_t* a,
                                         const uint32_t* b) {
    asm volatile(
        "mma.sync.aligned.m16n8k16.row.col.f32.bf16.bf16.f32 "
        "{%0,%1,%2,%3}, {%4,%5,%6,%7}, {%8,%9}, {%0,%1,%2,%3};"
        : "+f"(d[0]), "+f"(d[1]), "+f"(d[2]), "+f"(d[3])
        : "r"(a[0]), "r"(a[1]), "r"(a[2]), "r"(a[3]), "r"(b[0]), "r"(b[1]));
}
__device__ __forceinline__ uint32_t pack_bf16(float lo, float hi) {
    uint32_t r;
    asm("cvt.rn.bf16x2.f32 %0, %1, %2;" : "=r"(r) : "f"(hi), "f"(lo));
    return r;
}

// smem offsets.  Tile blocks: xs@0 (34816), es@34816 (34816).
// Prep (pe) blocks: Gs fp32 @0 (67584), As fp32 @135168, bk @145088.
// B blocks: Gbf@0, Bmbf@34816, Abf@69632, Pbf@73984, kqSb@79360, pkS@80000.
// s blocks (128/129) in R: redS@78336, sScr@78848, part1@79872, part2@80896.
#define OFF_GS   0
#define OFF_AS   135168
#define OFF_BK   145088
#define OFF_ES   34816
#define OFF_BMBF 34816
#define OFF_ABF  69632
#define OFF_PBF  73984
#define OFF_RED  78336
#define OFF_SCR  78848
#define OFF_KQB  79360
#define OFF_P1   79872
#define OFF_P2   80896
#define OFF_PKS  81920
#define DYN_SMEM 145664

// ---------------- fused kernel ------------------------------------------------
__global__ void __launch_bounds__(256) k_fused(
        const float* __restrict__ x,
        const float* __restrict__ w_q, const float* __restrict__ b_q,
        const float* __restrict__ w_k, const float* __restrict__ b_k,
        const float* __restrict__ w_v, const float* __restrict__ b_v,
        const float* __restrict__ w_o, const float* __restrict__ b_o,
        float* __restrict__ out) {
    extern __shared__ __align__(16) char dyn[];
    const int bid = blockIdx.x;
    const int t = threadIdx.x, wid = t >> 5, lane = t & 31;
    const float invN = 1.0f / (float)NPIX;

    // views
    __nv_bfloat16 (*xs)[136]   = (__nv_bfloat16(*)[136])dyn;
    __nv_bfloat16 (*es)[136]   = (__nv_bfloat16(*)[136])(dyn + OFF_ES);
    float (*Gs)[132]           = (float(*)[132])(dyn + OFF_GS);
    float (*As)[128]           = (float(*)[128])(dyn + OFF_AS);
    float* bkS                 = (float*)(dyn + OFF_BK);
    __nv_bfloat16 (*Gbf)[136]  = (__nv_bfloat16(*)[136])dyn;
    __nv_bfloat16 (*Bmbf)[136] = (__nv_bfloat16(*)[136])(dyn + OFF_BMBF);
    __nv_bfloat16 (*Abf)[136]  = (__nv_bfloat16(*)[136])(dyn + OFF_ABF);
    __nv_bfloat16 (*Pbf)[136]  = (__nv_bfloat16(*)[136])(dyn + OFF_PBF);
    float* kqSb = (float*)(dyn + OFF_KQB);
    float (*pkS)[8] = (float(*)[8])(dyn + OFF_PKS);

    // mma lane geometry
    const int m0 = (wid & 1) * 64;
    const int n0 = (wid >> 1) * 32;
    const int arow = lane & 15, acol8 = (lane >> 4) << 3;
    const int brow = lane & 7,  bcol8 = ((lane >> 3) & 1) << 3;
    const int gr = lane >> 2, ci = lane & 3;
    // packed-prep geometry
    const int c0 = t & 63;
    const int rr = t >> 6;

    const bool isB = (bid >= 100 && bid < 116);   // E'-computing blocks

    // =================== phase A =============================================
    if (bid < NTILE) {
        const int b = bid / NT, tile = bid % NT;
        const int nb = tile * 128;
        const float* xb = x + b*C*NPIX;

        #pragma unroll
        for (int it = 0; it < 16; it++) {
            const int e = t + it*256;
            const int row = e >> 5, q = e & 31;
            const float4 v = __ldg((const float4*)&xb[row*NPIX + nb + q*4]);
            *(uint2*)&xs[row][q*4] =
                make_uint2(pack_bf16(v.x, v.y), pack_bf16(v.z, v.w));
            float sv = (v.x + v.y) + (v.z + v.w);
            #pragma unroll
            for (int off = 16; off > 0; off >>= 1)
                sv += __shfl_down_sync(0xffffffffu, sv, off);
            if (lane == 0) g_sp[(b*NT + tile)*C + row] = sv;
        }
        __syncthreads();

        const uint32_t xbase = smem_u32(xs);
        float acc[4][4][4];
        #pragma unroll
        for (int i = 0; i < 4; i++)
            #pragma unroll
            for (int j = 0; j < 4; j++)
                #pragma unroll
                for (int q = 0; q < 4; q++) acc[i][j][q] = 0.f;

        #pragma unroll
        for (int ks = 0; ks < 8; ks++) {
            const int k0 = ks * 16;
            uint32_t af[4][4], bf[4][2];
            #pragma unroll
            for (int i = 0; i < 4; i++)
                ldsm_x4(af[i], xbase + ((m0 + 16*i + arow)*136 + k0 + acol8)*2);
            #pragma unroll
            for (int j = 0; j < 4; j++)
                ldsm_x2(bf[j], xbase + ((n0 + 8*j + brow)*136 + k0 + bcol8)*2);
            #pragma unroll
            for (int i = 0; i < 4; i++)
                #pragma unroll
                for (int j = 0; j < 4; j++)
                    mma16816(acc[i][j], af[i], bf[j]);
        }
        __nv_bfloat16* Gp = g_Gpb + (size_t)(b*NT + tile)*C*C;
        #pragma unroll
        for (int i = 0; i < 4; i++)
            #pragma unroll
            for (int j = 0; j < 4; j++) {
                const int row = m0 + 16*i + gr;
                const int col = n0 + 8*j + 2*ci;
                *(uint32_t*)&Gp[row*C + col] =
                    pack_bf16(acc[i][j][0], acc[i][j][1]);
                *(uint32_t*)&Gp[(row + 8)*C + col] =
                    pack_bf16(acc[i][j][2], acc[i][j][3]);
            }
    } else {
        // ---- prep: A = Wo Wv, Bm = Wk^T Wq (packed f32x2), bias vectors ----
        const int bid2 = bid - NTILE;          // 0..31
        const bool isA = bid2 < 16;
        const int r0s = (bid2 & 15) * 8;

        if (t < C) bkS[t] = __ldg(&b_k[t]);
        for (int e = t; e < 8*C; e += 256) {
            const int i = e >> 7, j = e & 127;
            As[i][j] = isA ? __ldg(&w_o[(r0s + i)*C + j])
                           : __ldg(&w_k[j*C + (r0s + i)]);
        }
        {
            const float* rhs = isA ? w_v : w_q;
            #pragma unroll
            for (int k = 0; k < 16; k++) {
                const int idx = t + k*256;
                const int row = idx >> 5, seg = idx & 31;
                *(float4*)&Gs[row][seg*4] = __ldg((const float4*)&rhs[row*C + seg*4]);
            }
        }
        __syncthreads();

        if (t < 128) {     // u[r] (A blocks) / kq[r] (Bm blocks)
            const int row = t >> 4, l = t & 15;
            const float* bv = isA ? b_v : b_q;
            float p = 0.f;
            #pragma unroll
            for (int j = 0; j < 8; j++)
                p += As[row][l*8 + j] * __ldg(&bv[l*8 + j]);
            p = red16(p);
            if (l == 0) (isA ? g_u : g_kq)[r0s + row] = p;
        }
        if (bid2 == 16 && t >= 128 && t < 160) {     // beta = bk.bq
            const int l = t - 128;
            float p = 0.f;
            #pragma unroll
            for (int j = 0; j < 4; j++) p += bkS[l*4 + j] * __ldg(&b_q[l*4 + j]);
            #pragma unroll
            for (int off = 16; off > 0; off >>= 1)
                p += __shfl_down_sync(0xffffffffu, p, off);
            if (l == 0) g_beta = p;
        }

        unsigned long long a0 = 0ull, a1 = 0ull, aw = 0ull;
        #pragma unroll 16
        for (int j = 0; j < 128; j++) {
            const unsigned long long r2 = *(const unsigned long long*)&Gs[j][2*c0];
            fma2(a0, dup2(As[rr][j]), r2);
            fma2(a1, dup2(As[rr + 4][j]), r2);
            fma2(aw, dup2(bkS[j]), r2);
        }
        float* dst = isA ? g_A : g_Bm;
        *(float2*)&dst[(r0s + rr)*C + 2*c0]     = unp2(a0);
        *(float2*)&dst[(r0s + rr + 4)*C + 2*c0] = unp2(a1);
        if (bid2 == 16 && rr == 0) *(float2*)&g_w2[2*c0] = unp2(aw);
    }

    // bar1: wait only where needed
    if (bid < 32 || isB || bid == 128 || bid == 129) gbar_wait(&g_bar1, NTOT);
    else                                            gbar_arrive(&g_bar1);

    // =================== phase R =============================================
    if (isB) {
        // prefetch A slab + Bm as bf16 (fp32 -> bf16 convert)
        const int bb = bid - 100;              // 0..15
        const int slab = bb & 7;
        const int r0s = slab * 16;
        #pragma unroll
        for (int k = 0; k < 4; k++) {          // Abf: 16x128 -> 1024 pairs
            const int idx = t + k*256;
            const int row = idx >> 6, cp = idx & 63;
            const float2 v = __ldcg((const float2*)&g_A[(r0s + row)*C + cp*2]);
            *(uint32_t*)&Abf[row][cp*2] = pack_bf16(v.x, v.y);
        }
        #pragma unroll
        for (int k = 0; k < 16; k++) {         // Bmbf: 128x128
            const int idx = t + k*256;
            const int row = idx >> 5, seg = idx & 31;
            const float4 v = __ldcg((const float4*)&g_Bm[row*C + seg*4]);
            *(uint2*)&Bmbf[row][seg*4] =
                make_uint2(pack_bf16(v.x, v.y), pack_bf16(v.z, v.w));
        }
        if (t < C) kqSb[t] = __ldcg(&g_kq[t]);
    }
    if (bid < 32) {
        // bf16 partial reduce -> bf16 G
        const int idx = bid*256 + t;               // 0..8191
        const int b = idx >> 12;
        const int e = (idx & 4095) * 4;
        const __nv_bfloat16* base = g_Gpb + (size_t)b*NT*C*C + e;
        float s0 = 0.f, s1 = 0.f, s2 = 0.f, s3 = 0.f;
        #pragma unroll
        for (int ch = 0; ch < NT; ch++) {
            const uint2 v = *(const uint2*)(base + (size_t)ch*C*C);
            const float2 lo = __bfloat1622float2(*(const __nv_bfloat162*)&v.x);
            const float2 hi = __bfloat1622float2(*(const __nv_bfloat162*)&v.y);
            s0 += lo.x; s1 += lo.y; s2 += hi.x; s3 += hi.y;
        }
        *(uint2*)&g_Gb16[b*C*C + e] =
            make_uint2(pack_bf16(s0, s1), pack_bf16(s2, s3));
    } else if (bid == 128 || bid == 129) {
        // s reduce + skq + t1 = Bm^T s + t2 = A s   (batch b)
        const int b = bid - 128;
        float* redS  = (float*)(dyn + OFF_RED);
        float* sScr  = (float*)(dyn + OFF_SCR);
        float* part1 = (float*)(dyn + OFF_P1);
        float* part2 = (float*)(dyn + OFF_P2);
        float sv = 0.f;
        if (t < C) {
            const float* sb = g_sp + b*NT*C + t;
            #pragma unroll
            for (int ch = 0; ch < NT; ch++) sv += sb[ch*C];
            g_s[b*C + t] = sv;
            sScr[t] = sv;
            redS[t] = sv * __ldcg(&g_kq[t]);
        }
        __syncthreads();
        if (t < 64) redS[t] += redS[t + 64];
        __syncthreads();
        if (t < 32) {
            float v = redS[t] + redS[t + 32];
            #pragma unroll
            for (int off = 16; off > 0; off >>= 1)
                v += __shfl_down_sync(0xffffffffu, v, off);
            if (t == 0) g_skq[b] = v;
        }
        // t1[c] = sum_j Bm[j][c] s[j]  (coalesced col access across threads)
        {
            const int col = t & 127, half = t >> 7;
            const int j0 = half * 64;
            float p = 0.f;
            #pragma unroll 16
            for (int jj = 0; jj < 64; jj++)
                p += __ldcg(&g_Bm[(j0 + jj)*C + col]) * sScr[j0 + jj];
            part1[half*128 + col] = p;
        }
        // t2[r] = sum_j A[r][j] s[j]
        {
            const int row = t & 127, half = t >> 7;
            const int j0 = half * 64;
            float p = 0.f;
            #pragma unroll 16
            for (int jj = 0; jj < 64; jj++)
                p += __ldcg(&g_A[row*C + j0 + jj]) * sScr[j0 + jj];
            part2[half*128 + row] = p;
        }
        __syncthreads();
        if (t < 128) {
            g_t1v[b*C + t] = part1[t] + part1[128 + t];
            g_t2v[b*C + t] = part2[t] + part2[128 + t];
        }
    }

    if (isB) gbar_wait(&g_bar2, NTOT);
    else     gbar_arrive(&g_bar2);

    // =================== phase B: 16 blocks, tensor-core E' ==================
    if (isB) {
        const int bb = bid - 100;
        const int b = bb >> 3, slab = bb & 7;
        const int r0s = slab * 16;

        #pragma unroll
        for (int k = 0; k < 8; k++) {          // stage bf16 G (32 KB)
            const int idx = t + k*256;
            const int row = idx >> 4, seg = idx & 15;
            *(uint4*)&Gbf[row][seg*8] =
                __ldcg((const uint4*)&g_Gb16[b*C*C + row*C + seg*8]);
        }
        __syncthreads();

        // mma1: P[16][128] = Abf @ G  (G symmetric => row-major = col operand)
        const uint32_t abase = smem_u32(Abf);
        const uint32_t gbase = smem_u32(Gbf);
        const int nw = wid * 16;               // warp's 16-col slice
        float accP[2][4];
        #pragma unroll
        for (int j = 0; j < 2; j++)
            #pragma unroll
            for (int q = 0; q < 4; q++) accP[j][q] = 0.f;
        #pragma unroll
        for (int ks = 0; ks < 8; ks++) {
            const int k0 = ks * 16;
            uint32_t af[4], bf[2][2];
            ldsm_x4(af, abase + (arow*136 + k0 + acol8)*2);
            #pragma unroll
            for (int j = 0; j < 2; j++)
                ldsm_x2(bf[j], gbase + ((nw + 8*j + brow)*136 + k0 + bcol8)*2);
            #pragma unroll
            for (int j = 0; j < 2; j++)
                mma16816(accP[j], af, bf[j]);
        }

        // e0 partials: pk[r] = sum_c P[r][c] kq[c]
        {
            const int cA0 = nw + 2*ci, cA1 = nw + 8 + 2*ci;
            float pk0 = accP[0][0]*kqSb[cA0] + accP[0][1]*kqSb[cA0+1]
                      + accP[1][0]*kqSb[cA1] + accP[1][1]*kqSb[cA1+1];
            float pk1 = accP[0][2]*kqSb[cA0] + accP[0][3]*kqSb[cA0+1]
                      + accP[1][2]*kqSb[cA1] + accP[1][3]*kqSb[cA1+1];
            pk0 += __shfl_down_sync(0xffffffffu, pk0, 2, 4);
            pk0 += __shfl_down_sync(0xffffffffu, pk0, 1, 4);
            pk1 += __shfl_down_sync(0xffffffffu, pk1, 2, 4);
            pk1 += __shfl_down_sync(0xffffffffu, pk1, 1, 4);
            if (ci == 0) { pkS[gr][wid] = pk0; pkS[gr + 8][wid] = pk1; }
        }
        // P -> bf16
        #pragma unroll
        for (int j = 0; j < 2; j++) {
            const int col = nw + 8*j + 2*ci;
            *(uint32_t*)&Pbf[gr][col]     = pack_bf16(accP[j][0], accP[j][1]);
            *(uint32_t*)&Pbf[gr + 8][col] = pack_bf16(accP[j][2], accP[j][3]);
        }
        __syncthreads();

        if (t < 16) {   // finalize e0 rows
            float pk = 0.f;
            #pragma unroll
            for (int w = 0; w < 8; w++) pk += pkS[t][w];
            const int r = r0s + t;
            const float ur = __ldg(&g_u[r]);
            g_e0[b*C + r] = invN*pk + invN*ur*g_skq[b]
                          + (invN*__ldcg(&g_t2v[b*C + r]) + ur)*g_beta
                          + __ldg(&b_o[r]);
        }

        // mma2: E'[16][128] = Pbf @ Bm  (Bm col operand via ldsm.trans)
        const uint32_t pbase = smem_u32(Pbf);
        const uint32_t bmbase = smem_u32(Bmbf);
        float accE[2][4];
        #pragma unroll
        for (int j = 0; j < 2; j++)
            #pragma unroll
            for (int q = 0; q < 4; q++) accE[j][q] = 0.f;
        #pragma unroll
        for (int ks = 0; ks < 8; ks++) {
            const int k0 = ks * 16;
            uint32_t af[4], bf[2][2];
            ldsm_x4(af, pbase + (arow*136 + k0 + acol8)*2);
            #pragma unroll
            for (int j = 0; j < 2; j++)
                ldsm_x2_trans(bf[j], bmbase + ((k0 + (lane & 15))*136 + nw + 8*j)*2);
            #pragma unroll
            for (int j = 0; j < 2; j++)
                mma16816(accE[j], af, bf[j]);
        }
        // epilogue: rank-1 terms + pack to g_Ebf  (t1/t2 precomputed in R)
        const float t2a = __ldcg(&g_t2v[b*C + r0s + gr]);
        const float t2b = __ldcg(&g_t2v[b*C + r0s + gr + 8]);
        #pragma unroll
        for (int j = 0; j < 2; j++) {
            const int col = nw + 8*j + 2*ci;
            const float w20 = __ldg(&g_w2[col]), w21 = __ldg(&g_w2[col + 1]);
            const float t10 = __ldcg(&g_t1v[b*C + col]);
            const float t11 = __ldcg(&g_t1v[b*C + col + 1]);
            {
                const int r = r0s + gr;
                const float ur = __ldg(&g_u[r]);
                const float cmn = invN*t2a + ur;
                *(uint32_t*)&g_Ebf[b*C*C + r*C + col] = pack_bf16(
                    invN*accE[j][0] + invN*ur*t10 + cmn*w20,
                    invN*accE[j][1] + invN*ur*t11 + cmn*w21);
            }
            {
                const int r = r0s + gr + 8;
                const float ur = __ldg(&g_u[r]);
                const float cmn = invN*t2b + ur;
                *(uint32_t*)&g_Ebf[b*C*C + r*C + col] = pack_bf16(
                    invN*accE[j][2] + invN*ur*t10 + cmn*w20,
                    invN*accE[j][3] + invN*ur*t11 + cmn*w21);
            }
        }
    }

    if (bid < NTILE) gbar_wait(&g_bar3, NTOT);
    else             gbar_arrive(&g_bar3);

    // =================== phase C: tile blocks out = X + E'X + e0 =============
    if (bid < NTILE) {
        const int b = bid / NT, tile = bid % NT;
        const int nb = tile * 128;
        const float* xb = x + b*C*NPIX;
        const __nv_bfloat16* Eb = g_Ebf + b*C*C;

        #pragma unroll
        for (int it = 0; it < 8; it++) {       // stage E' (32 KB) into es
            const int idx = t + it*256;
            const int row = idx >> 4, seg = idx & 15;
            *(uint4*)&es[row][seg*8] = __ldcg((const uint4*)&Eb[row*C + seg*8]);
        }
        __syncthreads();
        const uint32_t xbase = smem_u32(xs);
        const uint32_t ebase = smem_u32(es);

        float acc[4][4][4];
        #pragma unroll
        for (int i = 0; i < 4; i++)
            #pragma unroll
            for (int j = 0; j < 4; j++)
                #pragma unroll
                for (int q = 0; q < 4; q++) acc[i][j][q] = 0.f;

        #pragma unroll
        for (int ks = 0; ks < 8; ks++) {
            const int k0 = ks * 16;
            uint32_t af[4][4], bf[4][2];
            #pragma unroll
            for (int i = 0; i < 4; i++)
                ldsm_x4(af[i], ebase + ((m0 + 16*i + arow)*136 + k0 + acol8)*2);
            #pragma unroll
            for (int j = 0; j < 4; j++)
                ldsm_x2_trans(bf[j], xbase + ((k0 + (lane & 15))*136 + n0 + 8*j)*2);
            #pragma unroll
            for (int i = 0; i < 4; i++)
                #pragma unroll
                for (int j = 0; j < 4; j++)
                    mma16816(acc[i][j], af[i], bf[j]);
        }

        float* ob = out + b*C*NPIX;
        #pragma unroll
        for (int i = 0; i < 4; i++) {
            const int row = m0 + 16*i + gr;
            const float e0a = g_e0[b*C + row];
            const float e0b = g_e0[b*C + row + 8];
            #pragma unroll
            for (int j = 0; j < 4; j++) {
                const int col = n0 + 8*j + 2*ci;
                const float2 xa = *(const float2*)&xb[row*NPIX + nb + col];
                const float2 xc = *(const float2*)&xb[(row + 8)*NPIX + nb + col];
                *(float2*)&ob[row*NPIX + nb + col] =
                    make_float2(acc[i][j][0] + xa.x + e0a, acc[i][j][1] + xa.y + e0a);
                *(float2*)&ob[(row + 8)*NPIX + nb + col] =
                    make_float2(acc[i][j][2] + xc.x + e0b, acc[i][j][3] + xc.y + e0b);
            }
        }
    }
}

// ---------------- host launcher ----------------------------------------------
extern "C" void kernel_launch(void* const* d_in, const int* in_sizes, int n_in,
                              void* d_out, int out_size) {
    (void)in_sizes; (void)n_in; (void)out_size;
    const float* x   = (const float*)d_in[0];
    const float* w_q = (const float*)d_in[1];
    const float* b_q = (const float*)d_in[2];
    const float* w_k = (const float*)d_in[3];
    const float* b_k = (const float*)d_in[4];
    const float* w_v = (const float*)d_in[5];
    const float* b_v = (const float*)d_in[6];
    const float* w_o = (const float*)d_in[7];
    const float* b_o = (const float*)d_in[8];
    float* out = (float*)d_out;

    cudaFuncSetAttribute(k_fused, cudaFuncAttributeMaxDynamicSharedMemorySize,
                         DYN_SMEM);
    k_fused<<<NTOT, 256, DYN_SMEM>>>(x, w_q, b_q, w_k, b_k, w_v, b_v,
                                     w_o, b_o, out);
}